// round 1
// baseline (speedup 1.0000x reference)
#include <cuda_runtime.h>
#include <cstdint>

// Problem constants
#define B_    4096
#define LAT_  128
#define SEQ_  512
#define HID_  32
#define OUT_  64

#define WARPS_PER_BLOCK 8
#define THREADS (WARPS_PER_BLOCK * 32)

typedef unsigned long long ull;

__device__ __forceinline__ ull f2fma(ull a, ull b, ull c) {
    ull d;
    asm("fma.rn.f32x2 %0, %1, %2, %3;" : "=l"(d) : "l"(a), "l"(b), "l"(c));
    return d;
}
__device__ __forceinline__ ull f2pack(float lo, float hi) {
    ull r; asm("mov.b64 %0, {%1, %2};" : "=l"(r) : "f"(lo), "f"(hi)); return r;
}
__device__ __forceinline__ float f2sum(ull v) {
    float lo, hi; asm("mov.b64 {%0, %1}, %2;" : "=f"(lo), "=f"(hi) : "l"(v));
    return lo + hi;
}

// sigmoid / tanh via MUFU EX2 + RCP (near-fp32 accuracy, NaN/Inf safe)
__device__ __forceinline__ float sigf(float x) {
    float e = __expf(-x);
    return __fdividef(1.0f, 1.0f + e);
}
__device__ __forceinline__ float tanhf_fast(float x) {
    float e = __expf(-2.0f * x);
    return __fdividef(2.0f, 1.0f + e) - 1.0f;
}

__global__ void __launch_bounds__(THREADS, 1)
lstm_decoder_kernel(const float* __restrict__ z,
                    const float* __restrict__ init_W,
                    const float* __restrict__ init_b,
                    const float* __restrict__ W_hh,
                    const float* __restrict__ b_ih,
                    const float* __restrict__ b_hh,
                    const float* __restrict__ out_W,
                    const float* __restrict__ out_b,
                    float* __restrict__ y)
{
    // smem: padded stages for conflict-free register loads + per-warp h broadcast
    __shared__ __align__(16) float whh_s[128 * 34];   // 17408 B (pad 34 -> 2-way max)
    __shared__ __align__(16) float outw_s[64 * 34];   //  8704 B
    __shared__ __align__(16) float iwT_s[128 * 32];   // 16384 B (transposed init_W)
    __shared__ __align__(16) float zs[WARPS_PER_BLOCK * 128];  // 4096 B
    __shared__ __align__(16) float hb[WARPS_PER_BLOCK * 32];   // 1024 B

    const int tid  = threadIdx.x;
    const int w    = tid >> 5;      // warp in block
    const int j    = tid & 31;      // lane = hidden unit index
    const int b    = blockIdx.x * WARPS_PER_BLOCK + w;   // batch element

    // ---- stage weights into smem (coalesced global reads) ----
    for (int i = tid; i < 128 * 32; i += THREADS)
        whh_s[(i >> 5) * 34 + (i & 31)] = W_hh[i];
    for (int i = tid; i < 64 * 32; i += THREADS)
        outw_s[(i >> 5) * 34 + (i & 31)] = out_W[i];
    for (int i = tid; i < 32 * 128; i += THREADS) {
        int jj = i >> 7, kk = i & 127;
        iwT_s[kk * 32 + jj] = init_W[i];
    }
    // z row for this warp's batch element
    for (int kk = j; kk < 128; kk += 32)
        zs[w * 128 + kk] = z[(size_t)b * LAT_ + kk];
    __syncthreads();

    // ---- load per-lane weights into registers as f32x2 pairs ----
    ull Wi[16], Wf[16], Wg[16], Wo[16], Pa[16], Pb[16];
#pragma unroll
    for (int m = 0; m < 16; m++) {
        Wi[m] = *reinterpret_cast<const ull*>(&whh_s[(j      ) * 34 + 2 * m]);
        Wf[m] = *reinterpret_cast<const ull*>(&whh_s[(32 + j ) * 34 + 2 * m]);
        Wg[m] = *reinterpret_cast<const ull*>(&whh_s[(64 + j ) * 34 + 2 * m]);
        Wo[m] = *reinterpret_cast<const ull*>(&whh_s[(96 + j ) * 34 + 2 * m]);
        Pa[m] = *reinterpret_cast<const ull*>(&outw_s[(j     ) * 34 + 2 * m]);
        Pb[m] = *reinterpret_cast<const ull*>(&outw_s[(32 + j) * 34 + 2 * m]);
    }

    // ---- h0 = z @ init_W^T + init_b  (lane j computes h0_j) ----
    float h = init_b[j];
#pragma unroll 8
    for (int k = 0; k < 128; k++)
        h = fmaf(zs[w * 128 + k], iwT_s[k * 32 + j], h);
    float c = 0.0f;

    // gate bias constants (x input is zero, so W_ih term vanishes)
    const float bi  = b_ih[j]       + b_hh[j];
    const float bf  = b_ih[32 + j]  + b_hh[32 + j];
    const float bg  = b_ih[64 + j]  + b_hh[64 + j];
    const float bo  = b_ih[96 + j]  + b_hh[96 + j];
    const float ob0 = out_b[j];
    const float ob1 = out_b[32 + j];

    float* yo = y + (size_t)b * SEQ_ * OUT_;
    float* hbw = &hb[w * 32];

    // ---- main recurrence; projection of h_t fused into step t+1's k-loop ----
    for (int t = 0; t < SEQ_; t++) {
        __syncwarp();
        hbw[j] = h;
        __syncwarp();

        ull ai = f2pack(bi, 0.0f), af = f2pack(bf, 0.0f);
        ull ag = f2pack(bg, 0.0f), ao = f2pack(bo, 0.0f);
        ull y0 = f2pack(ob0, 0.0f), y1 = f2pack(ob1, 0.0f);
#pragma unroll
        for (int m = 0; m < 16; m++) {
            ull hp = *reinterpret_cast<const ull*>(&hbw[2 * m]);  // broadcast
            ai = f2fma(Wi[m], hp, ai);
            af = f2fma(Wf[m], hp, af);
            ag = f2fma(Wg[m], hp, ag);
            ao = f2fma(Wo[m], hp, ao);
            y0 = f2fma(Pa[m], hp, y0);
            y1 = f2fma(Pb[m], hp, y1);
        }
        if (t > 0) {   // projection of h_{t} (state entering this step) -> y[t-1]
            yo[(t - 1) * OUT_ + j]      = f2sum(y0);
            yo[(t - 1) * OUT_ + 32 + j] = f2sum(y1);
        }

        float gi = f2sum(ai), gf = f2sum(af), gg = f2sum(ag), go = f2sum(ao);
        float I = sigf(gi), F = sigf(gf), G = tanhf_fast(gg), O = sigf(go);
        c = fmaf(F, c, I * G);
        h = O * tanhf_fast(c);
    }

    // ---- peeled final projection (h after the last step) ----
    __syncwarp();
    hbw[j] = h;
    __syncwarp();
    {
        ull y0 = f2pack(ob0, 0.0f), y1 = f2pack(ob1, 0.0f);
#pragma unroll
        for (int m = 0; m < 16; m++) {
            ull hp = *reinterpret_cast<const ull*>(&hbw[2 * m]);
            y0 = f2fma(Pa[m], hp, y0);
            y1 = f2fma(Pb[m], hp, y1);
        }
        yo[(SEQ_ - 1) * OUT_ + j]      = f2sum(y0);
        yo[(SEQ_ - 1) * OUT_ + 32 + j] = f2sum(y1);
    }
}

extern "C" void kernel_launch(void* const* d_in, const int* in_sizes, int n_in,
                              void* d_out, int out_size)
{
    // metadata order: z, init_W, init_b, W_ih, W_hh, b_ih, b_hh, out_W, out_b
    const float* z      = (const float*)d_in[0];
    const float* init_W = (const float*)d_in[1];
    const float* init_b = (const float*)d_in[2];
    // d_in[3] = W_ih: unused (input sequence is all zeros)
    const float* W_hh   = (const float*)d_in[4];
    const float* b_ih   = (const float*)d_in[5];
    const float* b_hh   = (const float*)d_in[6];
    const float* out_W  = (const float*)d_in[7];
    const float* out_b  = (const float*)d_in[8];
    float* y            = (float*)d_out;

    dim3 grid(B_ / WARPS_PER_BLOCK);   // 512 blocks
    dim3 block(THREADS);               // 256 threads = 8 warps = 8 batch rows
    lstm_decoder_kernel<<<grid, block>>>(z, init_W, init_b, W_hh,
                                         b_ih, b_hh, out_W, out_b, y);
}